// round 13
// baseline (speedup 1.0000x reference)
#include <cuda_runtime.h>
#include <cstdint>

#define N_RES 8192
#define N_IN  256
#define BATCH 16
#define NREP  16          // accumulator replicas

// Scratch (device globals — runtime allocation prohibited)
__device__ __align__(256) float g_ZTR[NREP][N_RES * BATCH]; // replicated accumulators [rep][row][b]
__device__ __align__(256) float g_ST[N_RES * BATCH];        // state^T, [col][b]
__device__ __align__(256) float g_XT[N_IN * BATCH];         // x^T, [col][b]

__device__ __forceinline__ void red_add_v4(float* addr, float a, float b, float c, float d) {
    asm volatile("red.global.add.v4.f32 [%0], {%1, %2, %3, %4};"
                 :: "l"(addr), "f"(a), "f"(b), "f"(c), "f"(d)
                 : "memory");
}

// 1) prep: transpose state -> ST, x -> XT, zero replicas (proven-5.4us form)
__global__ void prep_kernel(const float* __restrict__ state,
                            const float* __restrict__ x) {
    int t = blockIdx.x * blockDim.x + threadIdx.x;
    if (t < N_RES * BATCH) {
        int b = t >> 13;
        int r = t & (N_RES - 1);
        g_ST[r * BATCH + b] = state[t];
    }
    if (t < N_IN * BATCH) {
        int b = t >> 8;
        int c = t & (N_IN - 1);
        g_XT[c * BATCH + b] = x[t];
    }
    float4* z = reinterpret_cast<float4*>(&g_ZTR[0][0]);
    int total4 = NREP * N_RES * BATCH / 4;
    for (int i = t; i < total4; i += gridDim.x * blockDim.x)
        z[i] = make_float4(0.f, 0.f, 0.f, 0.f);
}

// 2) combined SpMM, TPB=512: first in_blocks handle the input matrix
//    (gather from XT), remaining handle the reservoir (gather from ST).
//    4 lanes per nnz: lane quarter q owns batch slice [4q, 4q+4).
__global__ void __launch_bounds__(512)
spmm_all_kernel(const float* __restrict__ res_vals,
                const int*   __restrict__ res_rows,
                const int*   __restrict__ res_cols, int nnz_res,
                const float* __restrict__ in_vals,
                const int*   __restrict__ in_rows,
                const int*   __restrict__ in_cols, int nnz_in,
                int in_blocks) {
    const float* vals;
    const int*   rows;
    const int*   cols;
    const float* src_mat;
    int nnz, t;

    if (blockIdx.x < in_blocks) {
        vals = in_vals; rows = in_rows; cols = in_cols;
        src_mat = g_XT; nnz = nnz_in;
        t = blockIdx.x * blockDim.x + threadIdx.x;
    } else {
        vals = res_vals; rows = res_rows; cols = res_cols;
        src_mat = g_ST; nnz = nnz_res;
        t = (blockIdx.x - in_blocks) * blockDim.x + threadIdx.x;
    }

    int i = t >> 2;            // nnz index (8 nnz per warp)
    int q = t & 3;             // batch quarter
    if (i >= nnz) return;
    int rep = (t >> 5) & (NREP - 1);   // 16 warps/block -> each block covers all reps

    float val = __ldg(vals + i);       // quartet-redundant, sector-coalesced
    int   row = __ldg(rows + i);
    int   col = __ldg(cols + i);

    float4 s = __ldg(reinterpret_cast<const float4*>(src_mat) + col * 4 + q);
    float* dst = &g_ZTR[rep][row * BATCH + q * 4];
    red_add_v4(dst, val * s.x, val * s.y, val * s.z, val * s.w);
}

// 3) finish: reduce replicas + bias, erf; smem tile for coalesced output writes
__global__ void finish_kernel(const float* __restrict__ bias,
                              float* __restrict__ out) {
    __shared__ float tile[256];
    int t = threadIdx.x;                  // 0..255
    int base = blockIdx.x * 256;          // base index into ZTR flat space
    int gt = base + t;                    // flat [row][b] index
    int r = gt >> 4;

    float z = bias[r];
#pragma unroll
    for (int rep = 0; rep < NREP; rep++)
        z += g_ZTR[rep][gt];              // coalesced
    tile[t] = erff(z);
    __syncthreads();

    int b  = t >> 4;                      // 0..15
    int rl = t & 15;                      // 0..15
    int r0 = base >> 4;                   // first row of this block's tile
    out[b * N_RES + r0 + rl] = tile[rl * 16 + b];
}

extern "C" void kernel_launch(void* const* d_in, const int* in_sizes, int n_in,
                              void* d_out, int out_size) {
    const float* state    = (const float*)d_in[0];
    const float* x        = (const float*)d_in[1];
    const float* res_vals = (const float*)d_in[2];
    const int*   res_rows = (const int*)  d_in[3];
    const int*   res_cols = (const int*)  d_in[4];
    const float* res_bias = (const float*)d_in[5];
    const float* in_vals  = (const float*)d_in[6];
    const int*   in_rows  = (const int*)  d_in[7];
    const int*   in_cols  = (const int*)  d_in[8];
    float* out = (float*)d_out;

    int nnz_res = in_sizes[2];
    int nnz_in  = in_sizes[6];

    prep_kernel<<<2048, 256>>>(state, x);

    const int TPB = 512;
    int in_blocks  = (int)(((long long)nnz_in  * 4 + TPB - 1) / TPB);
    int res_blocks = (int)(((long long)nnz_res * 4 + TPB - 1) / TPB);
    spmm_all_kernel<<<in_blocks + res_blocks, TPB>>>(
        res_vals, res_rows, res_cols, nnz_res,
        in_vals, in_rows, in_cols, nnz_in, in_blocks);

    finish_kernel<<<N_RES * BATCH / 256, 256>>>(res_bias, out);
}

// round 14
// speedup vs baseline: 1.0603x; 1.0603x over previous
#include <cuda_runtime.h>
#include <cstdint>

#define N_RES 8192
#define N_IN  256
#define BATCH 16
#define NREP  16          // accumulator replicas

// Scratch (device globals — runtime allocation prohibited)
__device__ __align__(256) float g_ZTR[NREP][N_RES * BATCH]; // replicated accumulators [rep][row][b]
__device__ __align__(256) float g_ST[N_RES * BATCH];        // state^T, [col][b]
__device__ __align__(256) float g_XT[N_IN * BATCH];         // x^T, [col][b]

__device__ __forceinline__ void red_add_v4(float* addr, float a, float b, float c, float d) {
    asm volatile("red.global.add.v4.f32 [%0], {%1, %2, %3, %4};"
                 :: "l"(addr), "f"(a), "f"(b), "f"(c), "f"(d)
                 : "memory");
}

// 1) prep: transpose state -> ST, x -> XT, zero replicas (grid-stride)
__global__ void prep_kernel(const float* __restrict__ state,
                            const float* __restrict__ x) {
    int t = blockIdx.x * blockDim.x + threadIdx.x;
    if (t < N_RES * BATCH) {
        int b = t >> 13;
        int r = t & (N_RES - 1);
        g_ST[r * BATCH + b] = state[t];
    }
    if (t < N_IN * BATCH) {
        int b = t >> 8;
        int c = t & (N_IN - 1);
        g_XT[c * BATCH + b] = x[t];
    }
    float4* z = reinterpret_cast<float4*>(&g_ZTR[0][0]);
    int total4 = NREP * N_RES * BATCH / 4;
    for (int i = t; i < total4; i += gridDim.x * blockDim.x)
        z[i] = make_float4(0.f, 0.f, 0.f, 0.f);
}

// 2) combined SpMM: first in_blocks handle the input matrix (gather from XT),
//    remaining blocks handle the reservoir matrix (gather from ST).
//    4 lanes per nnz: lane quarter q owns batch slice [4q, 4q+4).
__global__ void spmm_all_kernel(const float* __restrict__ res_vals,
                                const int*   __restrict__ res_rows,
                                const int*   __restrict__ res_cols, int nnz_res,
                                const float* __restrict__ in_vals,
                                const int*   __restrict__ in_rows,
                                const int*   __restrict__ in_cols, int nnz_in,
                                int in_blocks) {
    const float* vals;
    const int*   rows;
    const int*   cols;
    const float* src_mat;
    int nnz, t;

    if (blockIdx.x < in_blocks) {
        vals = in_vals; rows = in_rows; cols = in_cols;
        src_mat = g_XT; nnz = nnz_in;
        t = blockIdx.x * blockDim.x + threadIdx.x;
    } else {
        vals = res_vals; rows = res_rows; cols = res_cols;
        src_mat = g_ST; nnz = nnz_res;
        t = (blockIdx.x - in_blocks) * blockDim.x + threadIdx.x;
    }

    int i = t >> 2;            // nnz index (8 nnz per warp)
    int q = t & 3;             // batch quarter
    if (i >= nnz) return;
    int rep = (t >> 5) & (NREP - 1);

    float val = vals[i];       // quartet-redundant, sector-coalesced
    int   row = rows[i];
    int   col = cols[i];

    float4 s = __ldg(reinterpret_cast<const float4*>(src_mat) + col * 4 + q);
    float* dst = &g_ZTR[rep][row * BATCH + q * 4];
    red_add_v4(dst, val * s.x, val * s.y, val * s.z, val * s.w);
}

// 3) reduce replicas + bias, erf, transposed write
__global__ void finish_kernel(const float* __restrict__ bias,
                              float* __restrict__ out) {
    int t = blockIdx.x * blockDim.x + threadIdx.x;
    if (t >= N_RES * BATCH) return;
    int r = t >> 4;
    int b = t & (BATCH - 1);

    float z = bias[r];
#pragma unroll
    for (int rep = 0; rep < NREP; rep++)
        z += g_ZTR[rep][t];
    out[b * N_RES + r] = erff(z);
}

extern "C" void kernel_launch(void* const* d_in, const int* in_sizes, int n_in,
                              void* d_out, int out_size) {
    const float* state    = (const float*)d_in[0];
    const float* x        = (const float*)d_in[1];
    const float* res_vals = (const float*)d_in[2];
    const int*   res_rows = (const int*)  d_in[3];
    const int*   res_cols = (const int*)  d_in[4];
    const float* res_bias = (const float*)d_in[5];
    const float* in_vals  = (const float*)d_in[6];
    const int*   in_rows  = (const int*)  d_in[7];
    const int*   in_cols  = (const int*)  d_in[8];
    float* out = (float*)d_out;

    int nnz_res = in_sizes[2];
    int nnz_in  = in_sizes[6];

    const int TPB = 256;

    prep_kernel<<<2048, TPB>>>(state, x);

    int in_blocks  = (int)(((long long)nnz_in  * 4 + TPB - 1) / TPB);
    int res_blocks = (int)(((long long)nnz_res * 4 + TPB - 1) / TPB);
    spmm_all_kernel<<<in_blocks + res_blocks, TPB>>>(
        res_vals, res_rows, res_cols, nnz_res,
        in_vals, in_rows, in_cols, nnz_in, in_blocks);

    finish_kernel<<<(N_RES * BATCH + TPB - 1) / TPB, TPB>>>(res_bias, out);
}